// round 2
// baseline (speedup 1.0000x reference)
#include <cuda_runtime.h>
#include <cuda_bf16.h>
#include <math.h>

// Problem constants
#define BB 2
#define SS 2048
#define HH 16
#define DD 64
#define HID 1024
#define NTOK (BB * SS)          // 4096
#define NEG_INF_ADD (-10000.0f)

// -------- scratch (allocation-free: __device__ globals) --------
__device__ float g_Q[(size_t)BB * HH * SS * DD];   // [b,h,s,d]
__device__ float g_K[(size_t)BB * HH * SS * DD];
__device__ float g_V[(size_t)BB * HH * SS * DD];

// ===================== QKV projection GEMM =====================
// C[NTOK, HID] = x[NTOK, HID] @ W[HID, HID] + bias, written into [b,h,s,d]
// 128x128 tile, BK=8, 256 threads, 8x8 microtile per thread.
#define BM 128
#define BN 128
#define BKK 8

__global__ __launch_bounds__(256, 2)
void qkv_gemm(const float* __restrict__ x,
              const float* __restrict__ Wq, const float* __restrict__ bq,
              const float* __restrict__ Wk, const float* __restrict__ bk,
              const float* __restrict__ Wv, const float* __restrict__ bv) {
    const float* W;
    const float* bias;
    float* out;
    int z = blockIdx.z;
    if (z == 0)      { W = Wq; bias = bq; out = g_Q; }
    else if (z == 1) { W = Wk; bias = bk; out = g_K; }
    else             { W = Wv; bias = bv; out = g_V; }

    __shared__ float As[BKK][BM + 4];   // padded: conflict-free transposed stores
    __shared__ float Bs[BKK][BN];

    const int tid = threadIdx.x;
    const int m0 = blockIdx.y * BM;
    const int n0 = blockIdx.x * BN;

    // A loader: thread -> (row = tid/2, kcol = (tid&1)*4), one float4 each
    const int aRow = tid >> 1;
    const int aCol = (tid & 1) * 4;
    // B loader: thread -> (krow = tid/32, col = (tid&31)*4), one float4 each
    const int bRow = tid >> 5;
    const int bCol = (tid & 31) * 4;

    const int ty = tid >> 4;   // 0..15
    const int tx = tid & 15;   // 0..15

    float acc[8][8];
#pragma unroll
    for (int i = 0; i < 8; i++)
#pragma unroll
        for (int j = 0; j < 8; j++) acc[i][j] = 0.f;

    for (int k0 = 0; k0 < HID; k0 += BKK) {
        float4 a4 = *(const float4*)&x[(size_t)(m0 + aRow) * HID + k0 + aCol];
        As[aCol + 0][aRow] = a4.x;
        As[aCol + 1][aRow] = a4.y;
        As[aCol + 2][aRow] = a4.z;
        As[aCol + 3][aRow] = a4.w;
        *(float4*)&Bs[bRow][bCol] =
            *(const float4*)&W[(size_t)(k0 + bRow) * HID + n0 + bCol];
        __syncthreads();

#pragma unroll
        for (int k = 0; k < BKK; k++) {
            float ar[8], br[8];
#pragma unroll
            for (int i = 0; i < 8; i += 4)
                *(float4*)&ar[i] = *(const float4*)&As[k][ty * 8 + i];
#pragma unroll
            for (int i = 0; i < 8; i += 4)
                *(float4*)&br[i] = *(const float4*)&Bs[k][tx * 8 + i];
#pragma unroll
            for (int i = 0; i < 8; i++)
#pragma unroll
                for (int j = 0; j < 8; j++)
                    acc[i][j] += ar[i] * br[j];
        }
        __syncthreads();
    }

    // epilogue: bias + scatter into [b,h,s,d]
#pragma unroll
    for (int i = 0; i < 8; i++) {
        int t = m0 + ty * 8 + i;
        int b = t >> 11;          // /2048
        int s = t & (SS - 1);
#pragma unroll
        for (int j = 0; j < 8; j++) {
            int c = n0 + tx * 8 + j;
            int h = c >> 6;
            int d = c & (DD - 1);
            out[(((size_t)(b * HH + h) * SS + s) * DD) + d] = acc[i][j] + bias[c];
        }
    }
}

// ===================== Flash attention (fp32) =====================
// 1 thread = 1 query row. 64 rows/block. K/V staged in shared, 64 keys/tile.
#define BR 64
#define BC 64

__global__ __launch_bounds__(BR, 5)
void flash_attn(const int* __restrict__ mask, float* __restrict__ out) {
    const int qtile = blockIdx.x;
    const int h     = blockIdx.y;
    const int b     = blockIdx.z;
    const int t     = threadIdx.x;

    const size_t headBase = ((size_t)(b * HH + h) * SS) * DD;
    const float* Qp = g_Q + headBase;
    const float* Kp = g_K + headBase;
    const float* Vp = g_V + headBase;

    __shared__ float4 Ks[BC * (DD / 4)];   // 64 keys x 16 float4
    __shared__ float4 Vs[BC * (DD / 4)];
    __shared__ float  adder_s[BC];

    const int qrow = qtile * BR + t;

    // q row in registers, pre-scaled by 1/sqrt(D)
    float q[DD];
    {
        const float4* Qg = (const float4*)(Qp + (size_t)qrow * DD);
#pragma unroll
        for (int i = 0; i < DD / 4; i++) {
            float4 v4 = Qg[i];
            q[4 * i + 0] = v4.x * 0.125f;
            q[4 * i + 1] = v4.y * 0.125f;
            q[4 * i + 2] = v4.z * 0.125f;
            q[4 * i + 3] = v4.w * 0.125f;
        }
    }

    float o[DD];
#pragma unroll
    for (int i = 0; i < DD; i++) o[i] = 0.f;
    float m = -INFINITY;
    float l = 0.f;

    for (int k0 = 0; k0 < SS; k0 += BC) {
        // stage K/V tile: 1024 float4 each, 64 threads -> 16 coalesced rounds
        {
            const float4* Kg = (const float4*)(Kp + (size_t)k0 * DD);
            const float4* Vg = (const float4*)(Vp + (size_t)k0 * DD);
#pragma unroll
            for (int i = 0; i < (BC * DD / 4) / BR; i++) {
                Ks[t + BR * i] = Kg[t + BR * i];
                Vs[t + BR * i] = Vg[t + BR * i];
            }
            adder_s[t] = (1.0f - (float)mask[b * SS + k0 + t]) * NEG_INF_ADD;
        }
        __syncthreads();

        for (int j = 0; j < BC; j++) {
            // dot(q, k_j): 4 accumulator chains for ILP
            float s0 = 0.f, s1 = 0.f, s2 = 0.f, s3 = 0.f;
#pragma unroll
            for (int i = 0; i < DD / 4; i++) {
                float4 k4 = Ks[j * (DD / 4) + i];
                s0 += q[4 * i + 0] * k4.x;
                s1 += q[4 * i + 1] * k4.y;
                s2 += q[4 * i + 2] * k4.z;
                s3 += q[4 * i + 3] * k4.w;
            }
            float s = (s0 + s1) + (s2 + s3) + adder_s[j];

            // online softmax with deferred rescale
            if (s > m) {
                float corr = __expf(m - s);   // exp(-inf)=0 on first key
                m = s;
                l *= corr;
#pragma unroll
                for (int i = 0; i < DD; i++) o[i] *= corr;
            }
            float p = __expf(s - m);
            l += p;
#pragma unroll
            for (int i = 0; i < DD / 4; i++) {
                float4 v4 = Vs[j * (DD / 4) + i];
                o[4 * i + 0] += p * v4.x;
                o[4 * i + 1] += p * v4.y;
                o[4 * i + 2] += p * v4.z;
                o[4 * i + 3] += p * v4.w;
            }
        }
        __syncthreads();
    }

    // write [b, s, h*D + d]
    float inv_l = 1.0f / l;
    float* outp = out + ((size_t)(b * SS + qrow)) * HID + h * DD;
#pragma unroll
    for (int i = 0; i < DD / 4; i++) {
        float4 r;
        r.x = o[4 * i + 0] * inv_l;
        r.y = o[4 * i + 1] * inv_l;
        r.z = o[4 * i + 2] * inv_l;
        r.w = o[4 * i + 3] * inv_l;
        *(float4*)&outp[4 * i] = r;
    }
}

// ===================== launch =====================
extern "C" void kernel_launch(void* const* d_in, const int* in_sizes, int n_in,
                              void* d_out, int out_size) {
    const float* x    = (const float*)d_in[0];
    const int*   mask = (const int*)d_in[1];
    const float* Wq   = (const float*)d_in[2];
    const float* bq   = (const float*)d_in[3];
    const float* Wk   = (const float*)d_in[4];
    const float* bk   = (const float*)d_in[5];
    const float* Wv   = (const float*)d_in[6];
    const float* bv   = (const float*)d_in[7];
    float* out = (float*)d_out;

    dim3 ggrid(HID / BN, NTOK / BM, 3);
    qkv_gemm<<<ggrid, 256>>>(x, Wq, bq, Wk, bk, Wv, bv);

    dim3 agrid(SS / BR, HH, BB);
    flash_attn<<<agrid, BR>>>(mask, out);
}

// round 5
// speedup vs baseline: 2.9756x; 2.9756x over previous
#include <cuda_runtime.h>
#include <cuda_bf16.h>
#include <math.h>
#include <stdint.h>

#define BB 2
#define SS 2048
#define HH 16
#define DD 64
#define HID 1024
#define NTOK (BB * SS)
#define LOG2E 1.4426950408889634f
#define QSCALE (0.125f * LOG2E)
#define MASKADD (-10000.0f * LOG2E)

// -------- scratch (allocation-free __device__ globals) --------
__device__ __nv_bfloat16 g_xh[(size_t)NTOK * HID];
__device__ __nv_bfloat16 g_xl[(size_t)NTOK * HID];
__device__ __nv_bfloat16 g_Wth[(size_t)3 * HID * HID];   // W^T [n][k] hi
__device__ __nv_bfloat16 g_Wtl[(size_t)3 * HID * HID];   // W^T [n][k] lo
__device__ __nv_bfloat16 g_Qh[(size_t)NTOK * HID];       // [b][h][s][d]
__device__ __nv_bfloat16 g_Ql[(size_t)NTOK * HID];
__device__ __nv_bfloat16 g_Kh[(size_t)NTOK * HID];
__device__ __nv_bfloat16 g_Kl[(size_t)NTOK * HID];
__device__ __nv_bfloat16 g_Vh[(size_t)NTOK * HID];
__device__ __nv_bfloat16 g_Vl[(size_t)NTOK * HID];

// ===================== helpers =====================
__device__ __forceinline__ uint32_t smem_u32(const void* p) {
    uint32_t a;
    asm("{ .reg .u64 t; cvta.to.shared.u64 t, %1; cvt.u32.u64 %0, t; }" : "=r"(a) : "l"(p));
    return a;
}
__device__ __forceinline__ uint32_t sw128(uint32_t o) { return o ^ ((o >> 3) & 0x70); }

__device__ __forceinline__ void ldsm4(uint32_t r[4], uint32_t addr) {
    asm volatile("ldmatrix.sync.aligned.m8n8.x4.shared.b16 {%0,%1,%2,%3}, [%4];"
                 : "=r"(r[0]), "=r"(r[1]), "=r"(r[2]), "=r"(r[3]) : "r"(addr));
}
__device__ __forceinline__ void ldsm4t(uint32_t r[4], uint32_t addr) {
    asm volatile("ldmatrix.sync.aligned.m8n8.x4.trans.shared.b16 {%0,%1,%2,%3}, [%4];"
                 : "=r"(r[0]), "=r"(r[1]), "=r"(r[2]), "=r"(r[3]) : "r"(addr));
}
__device__ __forceinline__ void mma16816(float c[4], const uint32_t a[4],
                                         uint32_t b0, uint32_t b1) {
    asm volatile(
        "mma.sync.aligned.m16n8k16.row.col.f32.bf16.bf16.f32 "
        "{%0,%1,%2,%3}, {%4,%5,%6,%7}, {%8,%9}, {%0,%1,%2,%3};"
        : "+f"(c[0]), "+f"(c[1]), "+f"(c[2]), "+f"(c[3])
        : "r"(a[0]), "r"(a[1]), "r"(a[2]), "r"(a[3]), "r"(b0), "r"(b1));
}
// pack hi-bf16s of two floats: bytes [a.2,a.3,b.2,b.3]
__device__ __forceinline__ uint32_t prmt_hi(float a, float b) {
    uint32_t d;
    asm("prmt.b32 %0, %1, %2, 0x7632;" : "=r"(d)
        : "r"(__float_as_uint(a)), "r"(__float_as_uint(b)));
    return d;
}
__device__ __forceinline__ float hi_trunc(float v) {
    return __uint_as_float(__float_as_uint(v) & 0xFFFF0000u);
}
// pack RN-bf16 of (e0 -> low, e1 -> high)
__device__ __forceinline__ uint32_t packlo(float e0, float e1) {
    uint32_t d;
    asm("cvt.rn.bf16x2.f32 %0, %1, %2;" : "=r"(d) : "f"(e1), "f"(e0));
    return d;
}
// exp2 via FFMA-only poly (no MUFU). x <= ~1; clamped below at -100.
__device__ __forceinline__ float exp2p(float x) {
    x = fmaxf(x, -100.0f);
    float t = x + 12582912.0f;                       // round-to-nearest int
    int   k = __float_as_int(t) - 0x4B400000;
    float f = x - (t - 12582912.0f);                 // frac in [-0.5, 0.5]
    float r = 1.3333558146428443e-3f;
    r = fmaf(r, f, 9.618129107628477e-3f);
    r = fmaf(r, f, 5.550410866482158e-2f);
    r = fmaf(r, f, 2.402265069591007e-1f);
    r = fmaf(r, f, 6.931471805599453e-1f);
    r = fmaf(r, f, 1.0f);
    return r * __int_as_float(0x3F800000 + (k << 23));
}

// ===================== prep kernels =====================
__global__ void split_x(const float* __restrict__ x) {
    int i = blockIdx.x * 256 + threadIdx.x;
    float v = x[i];
    float h = hi_trunc(v);
    g_xh[i] = __float2bfloat16(h);
    g_xl[i] = __float2bfloat16(v - h);
}

__global__ void split_w(const float* __restrict__ Wq, const float* __restrict__ Wk,
                        const float* __restrict__ Wv) {
    __shared__ float t[32][33];
    int z = blockIdx.z;
    const float* W = (z == 0) ? Wq : (z == 1) ? Wk : Wv;
    int tx = threadIdx.x, ty = threadIdx.y;
    t[ty][tx] = W[(size_t)(blockIdx.y * 32 + ty) * HID + blockIdx.x * 32 + tx];
    __syncthreads();
    int n = blockIdx.x * 32 + ty;
    int k = blockIdx.y * 32 + tx;
    float v = t[tx][ty];
    float h = hi_trunc(v);
    size_t o = (size_t)z * HID * HID + (size_t)n * HID + k;
    g_Wth[o] = __float2bfloat16(h);
    g_Wtl[o] = __float2bfloat16(v - h);
}

// ===================== QKV GEMM (mma.sync, split-bf16 3-term) =====================
// BM=128, BN=64, BK=64. 8 warps: wm=wid&3 (32 rows), wn=wid>>2 (32 cols).
// smem (static 48KB): Ah@0(16K) Al@16K Bh@32K(8K) Bl@40K, 128B SW128 rows.
__global__ __launch_bounds__(256)
void qkv_gemm_mma(const float* __restrict__ bq, const float* __restrict__ bk,
                  const float* __restrict__ bv) {
    __shared__ __align__(1024) char sm[49152];
    const int tid = threadIdx.x, lane = tid & 31, wid = tid >> 5;
    const int wm = wid & 3, wn = wid >> 2;
    const int z = blockIdx.z;
    const int m0 = blockIdx.y * 128;
    const int n0 = blockIdx.x * 64;

    const __nv_bfloat16* Wh = g_Wth + (size_t)z * HID * HID;
    const __nv_bfloat16* Wl = g_Wtl + (size_t)z * HID * HID;
    const float* bias = (z == 0) ? bq : (z == 1) ? bk : bv;
    __nv_bfloat16* outh = (z == 0) ? g_Qh : (z == 1) ? g_Kh : g_Vh;
    __nv_bfloat16* outl = (z == 0) ? g_Ql : (z == 1) ? g_Kl : g_Vl;

    const uint32_t smb = smem_u32(sm);

    float acc[2][4][4];
#pragma unroll
    for (int i = 0; i < 2; i++)
#pragma unroll
        for (int j = 0; j < 4; j++)
#pragma unroll
            for (int v = 0; v < 4; v++) acc[i][j][v] = 0.f;

    for (int k0 = 0; k0 < HID; k0 += 64) {
        __syncthreads();
        // A tiles: 128 rows x 8 chunks (16B)
#pragma unroll
        for (int j = 0; j < 4; j++) {
            int idx = tid + 256 * j;
            int row = idx >> 3, ch = idx & 7;
            uint32_t so = sw128((uint32_t)(row * 128 + ch * 16));
            size_t ga = (size_t)(m0 + row) * HID + k0 + ch * 8;
            *(uint4*)(sm + so)         = *(const uint4*)(g_xh + ga);
            *(uint4*)(sm + 16384 + so) = *(const uint4*)(g_xl + ga);
        }
        // B tiles: 64 rows x 8 chunks
#pragma unroll
        for (int j = 0; j < 2; j++) {
            int idx = tid + 256 * j;
            int row = idx >> 3, ch = idx & 7;
            uint32_t so = sw128((uint32_t)(row * 128 + ch * 16));
            size_t gb = (size_t)(n0 + row) * HID + k0 + ch * 8;
            *(uint4*)(sm + 32768 + so) = *(const uint4*)(Wh + gb);
            *(uint4*)(sm + 40960 + so) = *(const uint4*)(Wl + gb);
        }
        __syncthreads();

#pragma unroll
        for (int kk = 0; kk < 4; kk++) {
            const int cB = kk * 32 + (lane >> 4) * 16;
            const int rA = wm * 32 + (lane & 15);
            const int rB = wn * 32 + (lane & 15);
            uint32_t ah[2][4], al[2][4], bh[2][4], bl[2][4];
            ldsm4(ah[0], smb + sw128((uint32_t)(rA * 128 + cB)));
            ldsm4(ah[1], smb + sw128((uint32_t)((rA + 16) * 128 + cB)));
            ldsm4(al[0], smb + 16384 + sw128((uint32_t)(rA * 128 + cB)));
            ldsm4(al[1], smb + 16384 + sw128((uint32_t)((rA + 16) * 128 + cB)));
            ldsm4(bh[0], smb + 32768 + sw128((uint32_t)(rB * 128 + cB)));
            ldsm4(bh[1], smb + 32768 + sw128((uint32_t)((rB + 16) * 128 + cB)));
            ldsm4(bl[0], smb + 40960 + sw128((uint32_t)(rB * 128 + cB)));
            ldsm4(bl[1], smb + 40960 + sw128((uint32_t)((rB + 16) * 128 + cB)));
#pragma unroll
            for (int g = 0; g < 2; g++) {
#pragma unroll
                for (int mi = 0; mi < 2; mi++) {
                    mma16816(acc[mi][2 * g],     ah[mi], bh[g][0], bh[g][2]);
                    mma16816(acc[mi][2 * g + 1], ah[mi], bh[g][1], bh[g][3]);
                    mma16816(acc[mi][2 * g],     ah[mi], bl[g][0], bl[g][2]);
                    mma16816(acc[mi][2 * g + 1], ah[mi], bl[g][1], bl[g][3]);
                    mma16816(acc[mi][2 * g],     al[mi], bh[g][0], bh[g][2]);
                    mma16816(acc[mi][2 * g + 1], al[mi], bh[g][1], bh[g][3]);
                }
            }
        }
    }

    // epilogue: bias (+Q scale), split to hi/lo bf16, store [b,h,s,d]
    const float sc = (z == 0) ? QSCALE : 1.0f;
#pragma unroll
    for (int mi = 0; mi < 2; mi++) {
        int r0 = m0 + wm * 32 + mi * 16 + (lane >> 2);
#pragma unroll
        for (int nj = 0; nj < 4; nj++) {
            int col = n0 + wn * 32 + nj * 8 + 2 * (lane & 3);
            float b0v = __ldg(&bias[col]), b1v = __ldg(&bias[col + 1]);
#pragma unroll
            for (int half = 0; half < 2; half++) {
                int r = r0 + half * 8;
                float v0 = (acc[mi][nj][half * 2 + 0] + b0v) * sc;
                float v1 = (acc[mi][nj][half * 2 + 1] + b1v) * sc;
                size_t off = (((size_t)((r >> 11) * HH + (col >> 6)) * SS +
                               (r & (SS - 1))) * DD) + (col & (DD - 1));
                *(uint32_t*)(outh + off) = prmt_hi(v0, v1);
                *(uint32_t*)(outl + off) = packlo(v0 - hi_trunc(v0), v1 - hi_trunc(v1));
            }
        }
    }
}

// ===================== flash attention (mma.sync, split-bf16) =====================
// CTA: 128 q rows, 8 warps (16 rows each). Key chunks of 64.
// smem: phase1 Qh@0(16K) Ql@16K; phase2 Kh@0(8K) Kl@8K Vh@16K Vl@24K adder@32768.
__global__ __launch_bounds__(256)
void attn_mma(const int* __restrict__ mask, float* __restrict__ out) {
    __shared__ __align__(1024) char sm[33024];
    const int tid = threadIdx.x, lane = tid & 31, wid = tid >> 5;
    const int q0 = blockIdx.x * 128;
    const int h = blockIdx.y, b = blockIdx.z;
    const size_t hb = (size_t)(b * HH + h) * SS * DD;
    const uint32_t smb = smem_u32(sm);

    // ---- phase 1: Q tiles -> register A-frags ----
#pragma unroll
    for (int j = 0; j < 4; j++) {
        int idx = tid + 256 * j;
        int row = idx >> 3, ch = idx & 7;
        uint32_t so = sw128((uint32_t)(row * 128 + ch * 16));
        size_t g = hb + (size_t)(q0 + row) * DD + ch * 8;
        *(uint4*)(sm + so)         = *(const uint4*)(g_Qh + g);
        *(uint4*)(sm + 16384 + so) = *(const uint4*)(g_Ql + g);
    }
    __syncthreads();
    uint32_t qh[4][4], ql[4][4];
    {
        int r = wid * 16 + (lane & 15);
#pragma unroll
        for (int kk = 0; kk < 4; kk++) {
            int cB = kk * 32 + (lane >> 4) * 16;
            ldsm4(qh[kk], smb + sw128((uint32_t)(r * 128 + cB)));
            ldsm4(ql[kk], smb + 16384 + sw128((uint32_t)(r * 128 + cB)));
        }
    }
    __syncthreads();

    float ctx[8][4];
#pragma unroll
    for (int i = 0; i < 8; i++)
#pragma unroll
        for (int j = 0; j < 4; j++) ctx[i][j] = 0.f;
    float m0s = -1e30f, m1s = -1e30f, l0s = 0.f, l1s = 0.f;

    for (int c0 = 0; c0 < SS; c0 += 64) {
        // ---- stage K/V chunk ----
#pragma unroll
        for (int j = 0; j < 2; j++) {
            int idx = tid + 256 * j;
            int row = idx >> 3, ch = idx & 7;
            uint32_t so = sw128((uint32_t)(row * 128 + ch * 16));
            size_t g = hb + (size_t)(c0 + row) * DD + ch * 8;
            *(uint4*)(sm + so)         = *(const uint4*)(g_Kh + g);
            *(uint4*)(sm + 8192 + so)  = *(const uint4*)(g_Kl + g);
            *(uint4*)(sm + 16384 + so) = *(const uint4*)(g_Vh + g);
            *(uint4*)(sm + 24576 + so) = *(const uint4*)(g_Vl + g);
        }
        if (tid < 64) {
            int mv = mask[b * SS + c0 + tid];
            ((float*)(sm + 32768))[tid] = (float)(1 - mv) * MASKADD;
        }
        __syncthreads();

        // ---- S = Q K^T (log2 domain; Q pre-scaled) ----
        float sacc[8][4];
#pragma unroll
        for (int i = 0; i < 8; i++)
#pragma unroll
            for (int j = 0; j < 4; j++) sacc[i][j] = 0.f;

#pragma unroll
        for (int kk = 0; kk < 4; kk++) {
            const int cB = kk * 32 + (lane >> 4) * 16;
            const int rk = lane & 15;
            uint32_t kh[4][4], kl[4][4];
#pragma unroll
            for (int g = 0; g < 4; g++) {
                ldsm4(kh[g], smb + sw128((uint32_t)((rk + 16 * g) * 128 + cB)));
                ldsm4(kl[g], smb + 8192 + sw128((uint32_t)((rk + 16 * g) * 128 + cB)));
            }
#pragma unroll
            for (int g = 0; g < 4; g++) {
                mma16816(sacc[2 * g],     qh[kk], kh[g][0], kh[g][2]);
                mma16816(sacc[2 * g + 1], qh[kk], kh[g][1], kh[g][3]);
                mma16816(sacc[2 * g],     qh[kk], kl[g][0], kl[g][2]);
                mma16816(sacc[2 * g + 1], qh[kk], kl[g][1], kl[g][3]);
                mma16816(sacc[2 * g],     ql[kk], kh[g][0], kh[g][2]);
                mma16816(sacc[2 * g + 1], ql[kk], kh[g][1], kh[g][3]);
            }
        }

        // ---- online softmax (FFMA-only exp2) ----
        const float* adder = (const float*)(sm + 32768);
        const int kcol = 2 * (lane & 3);
        float mx0 = -1e30f, mx1 = -1e30f;
#pragma unroll
        for (int nj = 0; nj < 8; nj++) {
            float a0 = adder[nj * 8 + kcol], a1 = adder[nj * 8 + kcol + 1];
            sacc[nj][0] += a0; sacc[nj][1] += a1;
            sacc[nj][2] += a0; sacc[nj][3] += a1;
            mx0 = fmaxf(mx0, fmaxf(sacc[nj][0], sacc[nj][1]));
            mx1 = fmaxf(mx1, fmaxf(sacc[nj][2], sacc[nj][3]));
        }
        mx0 = fmaxf(mx0, __shfl_xor_sync(0xFFFFFFFFu, mx0, 1));
        mx0 = fmaxf(mx0, __shfl_xor_sync(0xFFFFFFFFu, mx0, 2));
        mx1 = fmaxf(mx1, __shfl_xor_sync(0xFFFFFFFFu, mx1, 1));
        mx1 = fmaxf(mx1, __shfl_xor_sync(0xFFFFFFFFu, mx1, 2));

        float mn0 = fmaxf(m0s, mx0), mn1 = fmaxf(m1s, mx1);
        float cr0 = exp2p(m0s - mn0), cr1 = exp2p(m1s - mn1);
        m0s = mn0; m1s = mn1;
        l0s *= cr0; l1s *= cr1;
#pragma unroll
        for (int nj = 0; nj < 8; nj++) {
            ctx[nj][0] *= cr0; ctx[nj][1] *= cr0;
            ctx[nj][2] *= cr1; ctx[nj][3] *= cr1;
        }
        float sum0 = 0.f, sum1 = 0.f;
#pragma unroll
        for (int nj = 0; nj < 8; nj++) {
            float p0 = exp2p(sacc[nj][0] - mn0);
            float p1 = exp2p(sacc[nj][1] - mn0);
            float p2 = exp2p(sacc[nj][2] - mn1);
            float p3 = exp2p(sacc[nj][3] - mn1);
            sum0 += p0 + p1; sum1 += p2 + p3;
            sacc[nj][0] = p0; sacc[nj][1] = p1;
            sacc[nj][2] = p2; sacc[nj][3] = p3;
        }
        sum0 += __shfl_xor_sync(0xFFFFFFFFu, sum0, 1);
        sum0 += __shfl_xor_sync(0xFFFFFFFFu, sum0, 2);
        sum1 += __shfl_xor_sync(0xFFFFFFFFu, sum1, 1);
        sum1 += __shfl_xor_sync(0xFFFFFFFFu, sum1, 2);
        l0s += sum0; l1s += sum1;

        // ---- ctx += P V (P split hi/lo in registers) ----
#pragma unroll
        for (int kg = 0; kg < 4; kg++) {
            const float* s0 = sacc[2 * kg];
            const float* s1 = sacc[2 * kg + 1];
            uint32_t ph[4], pl[4];
            ph[0] = prmt_hi(s0[0], s0[1]);
            ph[1] = prmt_hi(s0[2], s0[3]);
            ph[2] = prmt_hi(s1[0], s1[1]);
            ph[3] = prmt_hi(s1[2], s1[3]);
            pl[0] = packlo(s0[0] - hi_trunc(s0[0]), s0[1] - hi_trunc(s0[1]));
            pl[1] = packlo(s0[2] - hi_trunc(s0[2]), s0[3] - hi_trunc(s0[3]));
            pl[2] = packlo(s1[0] - hi_trunc(s1[0]), s1[1] - hi_trunc(s1[1]));
            pl[3] = packlo(s1[2] - hi_trunc(s1[2]), s1[3] - hi_trunc(s1[3]));
            const int rv = kg * 16 + (lane & 15);
#pragma unroll
            for (int dg = 0; dg < 4; dg++) {
                const int cB = dg * 32 + (lane >> 4) * 16;
                uint32_t vh[4], vl[4];
                ldsm4t(vh, smb + 16384 + sw128((uint32_t)(rv * 128 + cB)));
                ldsm4t(vl, smb + 24576 + sw128((uint32_t)(rv * 128 + cB)));
                mma16816(ctx[2 * dg],     ph, vh[0], vh[1]);
                mma16816(ctx[2 * dg + 1], ph, vh[2], vh[3]);
                mma16816(ctx[2 * dg],     ph, vl[0], vl[1]);
                mma16816(ctx[2 * dg + 1], ph, vl[2], vl[3]);
                mma16816(ctx[2 * dg],     pl, vh[0], vh[1]);
                mma16816(ctx[2 * dg + 1], pl, vh[2], vh[3]);
            }
        }
        __syncthreads();
    }

    // ---- write out [b, s, h*64 + d] ----
    const float inv0 = 1.0f / l0s, inv1 = 1.0f / l1s;
    const int r0 = q0 + wid * 16 + (lane >> 2);
    const int dbase = 2 * (lane & 3);
#pragma unroll
    for (int nj = 0; nj < 8; nj++) {
        int d = nj * 8 + dbase;
        float2 v0 = make_float2(ctx[nj][0] * inv0, ctx[nj][1] * inv0);
        float2 v1 = make_float2(ctx[nj][2] * inv1, ctx[nj][3] * inv1);
        *(float2*)&out[(size_t)(b * SS + r0) * HID + h * DD + d] = v0;
        *(float2*)&out[(size_t)(b * SS + r0 + 8) * HID + h * DD + d] = v1;
    }
}

// ===================== launch =====================
extern "C" void kernel_launch(void* const* d_in, const int* in_sizes, int n_in,
                              void* d_out, int out_size) {
    const float* x    = (const float*)d_in[0];
    const int*   mask = (const int*)d_in[1];
    const float* Wq   = (const float*)d_in[2];
    const float* bq   = (const float*)d_in[3];
    const float* Wk   = (const float*)d_in[4];
    const float* bk   = (const float*)d_in[5];
    const float* Wv   = (const float*)d_in[6];
    const float* bv   = (const float*)d_in[7];
    float* out = (float*)d_out;

    split_x<<<(NTOK * HID) / 256, 256>>>(x);
    dim3 wgrid(HID / 32, HID / 32, 3);
    split_w<<<wgrid, dim3(32, 32)>>>(Wq, Wk, Wv);

    dim3 ggrid(HID / 64, NTOK / 128, 3);
    qkv_gemm_mma<<<ggrid, 256>>>(bq, bk, bv);

    dim3 agrid(SS / 128, HH, BB);
    attn_mma<<<agrid, 256>>>(mask, out);
}

// round 6
// speedup vs baseline: 3.8599x; 1.2972x over previous
#include <cuda_runtime.h>
#include <cuda_bf16.h>
#include <math.h>
#include <stdint.h>

#define BB 2
#define SS 2048
#define HH 16
#define DD 64
#define HID 1024
#define NTOK (BB * SS)
#define LOG2E 1.4426950408889634f
#define QSCALE (0.125f * LOG2E)
#define MASKADD (-10000.0f * LOG2E)

// -------- scratch (allocation-free __device__ globals) --------
__device__ __nv_bfloat16 g_xh[(size_t)NTOK * HID];
__device__ __nv_bfloat16 g_xl[(size_t)NTOK * HID];
__device__ __nv_bfloat16 g_Wth[(size_t)3 * HID * HID];   // W^T [n][k] hi
__device__ __nv_bfloat16 g_Wtl[(size_t)3 * HID * HID];   // W^T [n][k] lo
__device__ __nv_bfloat16 g_Qh[(size_t)NTOK * HID];       // [b][h][s][d]
__device__ __nv_bfloat16 g_Ql[(size_t)NTOK * HID];
__device__ __nv_bfloat16 g_Kh[(size_t)NTOK * HID];
__device__ __nv_bfloat16 g_Vh[(size_t)NTOK * HID];
__device__ __nv_bfloat16 g_Vl[(size_t)NTOK * HID];

// ===================== helpers =====================
__device__ __forceinline__ uint32_t smem_u32(const void* p) {
    uint32_t a;
    asm("{ .reg .u64 t; cvta.to.shared.u64 t, %1; cvt.u32.u64 %0, t; }" : "=r"(a) : "l"(p));
    return a;
}
__device__ __forceinline__ uint32_t sw128(uint32_t o) { return o ^ ((o >> 3) & 0x70); }

__device__ __forceinline__ void ldsm4(uint32_t r[4], uint32_t addr) {
    asm volatile("ldmatrix.sync.aligned.m8n8.x4.shared.b16 {%0,%1,%2,%3}, [%4];"
                 : "=r"(r[0]), "=r"(r[1]), "=r"(r[2]), "=r"(r[3]) : "r"(addr));
}
__device__ __forceinline__ void ldsm4t(uint32_t r[4], uint32_t addr) {
    asm volatile("ldmatrix.sync.aligned.m8n8.x4.trans.shared.b16 {%0,%1,%2,%3}, [%4];"
                 : "=r"(r[0]), "=r"(r[1]), "=r"(r[2]), "=r"(r[3]) : "r"(addr));
}
__device__ __forceinline__ void mma16816(float c[4], const uint32_t a[4],
                                         uint32_t b0, uint32_t b1) {
    asm volatile(
        "mma.sync.aligned.m16n8k16.row.col.f32.bf16.bf16.f32 "
        "{%0,%1,%2,%3}, {%4,%5,%6,%7}, {%8,%9}, {%0,%1,%2,%3};"
        : "+f"(c[0]), "+f"(c[1]), "+f"(c[2]), "+f"(c[3])
        : "r"(a[0]), "r"(a[1]), "r"(a[2]), "r"(a[3]), "r"(b0), "r"(b1));
}
// truncation-split (P in PV keeps all 3 terms; bias harmless there)
__device__ __forceinline__ uint32_t prmt_hi(float a, float b) {
    uint32_t d;
    asm("prmt.b32 %0, %1, %2, 0x7632;" : "=r"(d)
        : "r"(__float_as_uint(a)), "r"(__float_as_uint(b)));
    return d;
}
__device__ __forceinline__ float hi_trunc(float v) {
    return __uint_as_float(__float_as_uint(v) & 0xFFFF0000u);
}
// pack RN-bf16 of (e0 -> low half, e1 -> high half)
__device__ __forceinline__ uint32_t packlo(float e0, float e1) {
    uint32_t d;
    asm("cvt.rn.bf16x2.f32 %0, %1, %2;" : "=r"(d) : "f"(e1), "f"(e0));
    return d;
}
// FFMA-only exp2
__device__ __forceinline__ float exp2p(float x) {
    x = fmaxf(x, -100.0f);
    float t = x + 12582912.0f;
    int   k = __float_as_int(t) - 0x4B400000;
    float f = x - (t - 12582912.0f);
    float r = 1.3333558146428443e-3f;
    r = fmaf(r, f, 9.618129107628477e-3f);
    r = fmaf(r, f, 5.550410866482158e-2f);
    r = fmaf(r, f, 2.402265069591007e-1f);
    r = fmaf(r, f, 6.931471805599453e-1f);
    r = fmaf(r, f, 1.0f);
    return r * __int_as_float(0x3F800000 + (k << 23));
}
// cp.async 16B
__device__ __forceinline__ void cpa16(uint32_t s, const void* g) {
    asm volatile("cp.async.cg.shared.global [%0], [%1], 16;" :: "r"(s), "l"(g));
}
#define CPA_COMMIT() asm volatile("cp.async.commit_group;")
#define CPA_WAIT1()  asm volatile("cp.async.wait_group 1;")
#define CPA_WAIT0()  asm volatile("cp.async.wait_group 0;")

// ===================== prep kernels (RN hi, residual lo) =====================
__global__ void split_x(const float* __restrict__ x) {
    int i = blockIdx.x * 256 + threadIdx.x;
    float v = x[i];
    __nv_bfloat16 h = __float2bfloat16(v);          // RN
    g_xh[i] = h;
    g_xl[i] = __float2bfloat16(v - __bfloat162float(h));
}

__global__ void split_w(const float* __restrict__ Wq, const float* __restrict__ Wk,
                        const float* __restrict__ Wv) {
    __shared__ float t[32][33];
    int z = blockIdx.z;
    const float* W = (z == 0) ? Wq : (z == 1) ? Wk : Wv;
    int tx = threadIdx.x, ty = threadIdx.y;
    t[ty][tx] = W[(size_t)(blockIdx.y * 32 + ty) * HID + blockIdx.x * 32 + tx];
    __syncthreads();
    int n = blockIdx.x * 32 + ty;
    int k = blockIdx.y * 32 + tx;
    float v = t[tx][ty];
    __nv_bfloat16 h = __float2bfloat16(v);          // RN
    size_t o = (size_t)z * HID * HID + (size_t)n * HID + k;
    g_Wth[o] = h;
    g_Wtl[o] = __float2bfloat16(v - __bfloat162float(h));
}

// ===================== QKV GEMM (mma.sync, 2-stage cp.async) =====================
// BM=128, BN=64, BK=64. stage: Ah@0(16K) Al@16K Bh@32K Bl@40K = 48K; 2 stages.
#define GSTAGE 49152
#define NCHUNK 16

__global__ __launch_bounds__(256, 2)
void qkv_gemm_mma(const float* __restrict__ bq, const float* __restrict__ bk,
                  const float* __restrict__ bv) {
    extern __shared__ __align__(1024) char sm[];
    const int tid = threadIdx.x, lane = tid & 31, wid = tid >> 5;
    const int wm = wid & 3, wn = wid >> 2;
    const int z = blockIdx.z;
    const int m0 = blockIdx.y * 128;
    const int n0 = blockIdx.x * 64;

    const __nv_bfloat16* Wh = g_Wth + (size_t)z * HID * HID;
    const __nv_bfloat16* Wl = g_Wtl + (size_t)z * HID * HID;
    const float* bias = (z == 0) ? bq : (z == 1) ? bk : bv;
    const uint32_t smb = smem_u32(sm);

    // loader geometry (shared by all chunks)
    const int arow = tid >> 1;                 // A: 128 rows x 2 chunks-of-64B? no:
    // A tile: 128 rows x 8 x 16B = 1024 chunks; 256 threads x 4
    // B tile: 64 rows x 8 x 16B = 512 chunks; 256 threads x 2
    auto issue = [&](int c, int s) {
        char* sb = sm + s * GSTAGE;
        const int k0 = c * 64;
#pragma unroll
        for (int j = 0; j < 4; j++) {
            int idx = tid + 256 * j;
            int row = idx >> 3, ch = idx & 7;
            uint32_t so = sw128((uint32_t)(row * 128 + ch * 16));
            size_t ga = (size_t)(m0 + row) * HID + k0 + ch * 8;
            cpa16(smb + s * GSTAGE + so,         g_xh + ga);
            cpa16(smb + s * GSTAGE + 16384 + so, g_xl + ga);
        }
#pragma unroll
        for (int j = 0; j < 2; j++) {
            int idx = tid + 256 * j;
            int row = idx >> 3, ch = idx & 7;
            uint32_t so = sw128((uint32_t)(row * 128 + ch * 16));
            size_t gb = (size_t)(n0 + row) * HID + k0 + ch * 8;
            cpa16(smb + s * GSTAGE + 32768 + so, Wh + gb);
            cpa16(smb + s * GSTAGE + 40960 + so, Wl + gb);
        }
        (void)sb;
        CPA_COMMIT();
    };

    float acc[2][4][4];
#pragma unroll
    for (int i = 0; i < 2; i++)
#pragma unroll
        for (int j = 0; j < 4; j++)
#pragma unroll
            for (int v = 0; v < 4; v++) acc[i][j][v] = 0.f;

    issue(0, 0);
    issue(1, 1);

    for (int c = 0; c < NCHUNK; c++) {
        const int s = c & 1;
        const uint32_t sb = smb + s * GSTAGE;
        if (c + 2 < NCHUNK) CPA_WAIT1(); else CPA_WAIT0();
        __syncthreads();

#pragma unroll
        for (int kk = 0; kk < 4; kk++) {
            const int cB = kk * 32 + (lane >> 4) * 16;
            const int rA = wm * 32 + (lane & 15);
            const int rB = wn * 32 + (lane & 15);
            uint32_t ah[2][4], al[2][4], bh[2][4], bl[2][4];
            ldsm4(ah[0], sb + sw128((uint32_t)(rA * 128 + cB)));
            ldsm4(ah[1], sb + sw128((uint32_t)((rA + 16) * 128 + cB)));
            ldsm4(al[0], sb + 16384 + sw128((uint32_t)(rA * 128 + cB)));
            ldsm4(al[1], sb + 16384 + sw128((uint32_t)((rA + 16) * 128 + cB)));
            ldsm4(bh[0], sb + 32768 + sw128((uint32_t)(rB * 128 + cB)));
            ldsm4(bh[1], sb + 32768 + sw128((uint32_t)((rB + 16) * 128 + cB)));
            ldsm4(bl[0], sb + 40960 + sw128((uint32_t)(rB * 128 + cB)));
            ldsm4(bl[1], sb + 40960 + sw128((uint32_t)((rB + 16) * 128 + cB)));
#pragma unroll
            for (int g = 0; g < 2; g++) {
#pragma unroll
                for (int mi = 0; mi < 2; mi++) {
                    mma16816(acc[mi][2 * g],     ah[mi], bh[g][0], bh[g][2]);
                    mma16816(acc[mi][2 * g + 1], ah[mi], bh[g][1], bh[g][3]);
                    mma16816(acc[mi][2 * g],     ah[mi], bl[g][0], bl[g][2]);
                    mma16816(acc[mi][2 * g + 1], ah[mi], bl[g][1], bl[g][3]);
                    mma16816(acc[mi][2 * g],     al[mi], bh[g][0], bh[g][2]);
                    mma16816(acc[mi][2 * g + 1], al[mi], bh[g][1], bh[g][3]);
                }
            }
        }
        __syncthreads();
        if (c + 2 < NCHUNK) issue(c + 2, s);
    }

    // epilogue: bias (+Q scale), RN hi + residual lo, store [b,h,s,d]
    __nv_bfloat16* outh = (z == 0) ? g_Qh : (z == 1) ? g_Kh : g_Vh;
    __nv_bfloat16* outl = (z == 0) ? g_Ql : g_Vl;   // z==1 lo never consumed
    const float sc = (z == 0) ? QSCALE : 1.0f;
#pragma unroll
    for (int mi = 0; mi < 2; mi++) {
        int r0 = m0 + wm * 32 + mi * 16 + (lane >> 2);
#pragma unroll
        for (int nj = 0; nj < 4; nj++) {
            int col = n0 + wn * 32 + nj * 8 + 2 * (lane & 3);
            float b0v = __ldg(&bias[col]), b1v = __ldg(&bias[col + 1]);
#pragma unroll
            for (int half = 0; half < 2; half++) {
                int r = r0 + half * 8;
                float v0 = (acc[mi][nj][half * 2 + 0] + b0v) * sc;
                float v1 = (acc[mi][nj][half * 2 + 1] + b1v) * sc;
                size_t off = (((size_t)((r >> 11) * HH + (col >> 6)) * SS +
                               (r & (SS - 1))) * DD) + (col & (DD - 1));
                uint32_t hp = packlo(v0, v1);                       // RN hi pair
                *(uint32_t*)(outh + off) = hp;
                if (z != 1) {
                    float hf0 = __uint_as_float(hp << 16);
                    float hf1 = __uint_as_float(hp & 0xFFFF0000u);
                    *(uint32_t*)(outl + off) = packlo(v0 - hf0, v1 - hf1);
                }
            }
        }
    }
}

// ===================== flash attention (mma.sync, 2-stage cp.async) =====================
// CTA: 128 q rows, 8 warps. 64 keys/chunk, 32 chunks.
// stage s@s*24576: Kh@0(8K) Vh@8192 Vl@16384. adder@49152+s*256.
// prologue Q staging: Qh@0(16K) Ql@16384(16K).
#define ASTAGE 24576
#define AADDER 49152
#define ASMEM  (AADDER + 512)
#define ACH 32

__global__ __launch_bounds__(256, 2)
void attn_mma(const int* __restrict__ mask, float* __restrict__ out) {
    extern __shared__ __align__(1024) char sm[];
    const int tid = threadIdx.x, lane = tid & 31, wid = tid >> 5;
    const int q0 = blockIdx.x * 128;
    const int h = blockIdx.y, b = blockIdx.z;
    const size_t hb = (size_t)(b * HH + h) * SS * DD;
    const uint32_t smb = smem_u32(sm);

    // ---- prologue: stage Q hi/lo, read A-frags ----
#pragma unroll
    for (int j = 0; j < 4; j++) {
        int idx = tid + 256 * j;
        int row = idx >> 3, ch = idx & 7;
        uint32_t so = sw128((uint32_t)(row * 128 + ch * 16));
        size_t g = hb + (size_t)(q0 + row) * DD + ch * 8;
        *(uint4*)(sm + so)         = *(const uint4*)(g_Qh + g);
        *(uint4*)(sm + 16384 + so) = *(const uint4*)(g_Ql + g);
    }
    __syncthreads();
    uint32_t qh[4][4], ql[4][4];
    {
        int r = wid * 16 + (lane & 15);
#pragma unroll
        for (int kk = 0; kk < 4; kk++) {
            int cB = kk * 32 + (lane >> 4) * 16;
            ldsm4(qh[kk], smb + sw128((uint32_t)(r * 128 + cB)));
            ldsm4(ql[kk], smb + 16384 + sw128((uint32_t)(r * 128 + cB)));
        }
    }
    __syncthreads();

    auto issue = [&](int c, int s) {
        const uint32_t sb = smb + s * ASTAGE;
        const int c0 = c * 64;
#pragma unroll
        for (int j = 0; j < 2; j++) {
            int idx = tid + 256 * j;
            int row = idx >> 3, ch = idx & 7;
            uint32_t so = sw128((uint32_t)(row * 128 + ch * 16));
            size_t g = hb + (size_t)(c0 + row) * DD + ch * 8;
            cpa16(sb + so,         g_Kh + g);
            cpa16(sb + 8192 + so,  g_Vh + g);
            cpa16(sb + 16384 + so, g_Vl + g);
        }
        if (tid < 64) {
            int mv = mask[b * SS + c0 + tid];
            ((float*)(sm + AADDER + s * 256))[tid] = (float)(1 - mv) * MASKADD;
        }
        CPA_COMMIT();
    };

    float ctx[8][4];
#pragma unroll
    for (int i = 0; i < 8; i++)
#pragma unroll
        for (int j = 0; j < 4; j++) ctx[i][j] = 0.f;
    float m0s = -1e30f, m1s = -1e30f, l0s = 0.f, l1s = 0.f;

    issue(0, 0);
    issue(1, 1);

    for (int c = 0; c < ACH; c++) {
        const int s = c & 1;
        const uint32_t sb = smb + s * ASTAGE;
        if (c + 2 < ACH) CPA_WAIT1(); else CPA_WAIT0();
        __syncthreads();

        // ---- S = Q K^T (2-term: qh*kh + ql*kh) ----
        float sacc[8][4];
#pragma unroll
        for (int i = 0; i < 8; i++)
#pragma unroll
            for (int j = 0; j < 4; j++) sacc[i][j] = 0.f;

#pragma unroll
        for (int kk = 0; kk < 4; kk++) {
            const int cB = kk * 32 + (lane >> 4) * 16;
            const int rk = lane & 15;
#pragma unroll
            for (int g = 0; g < 4; g++) {
                uint32_t kh[4];
                ldsm4(kh, sb + sw128((uint32_t)((rk + 16 * g) * 128 + cB)));
                mma16816(sacc[2 * g],     qh[kk], kh[0], kh[2]);
                mma16816(sacc[2 * g + 1], qh[kk], kh[1], kh[3]);
                mma16816(sacc[2 * g],     ql[kk], kh[0], kh[2]);
                mma16816(sacc[2 * g + 1], ql[kk], kh[1], kh[3]);
            }
        }

        // ---- online softmax (log2 domain) ----
        const float* adder = (const float*)(sm + AADDER + s * 256);
        const int kcol = 2 * (lane & 3);
        float mx0 = -1e30f, mx1 = -1e30f;
#pragma unroll
        for (int nj = 0; nj < 8; nj++) {
            float a0 = adder[nj * 8 + kcol], a1 = adder[nj * 8 + kcol + 1];
            sacc[nj][0] += a0; sacc[nj][1] += a1;
            sacc[nj][2] += a0; sacc[nj][3] += a1;
            mx0 = fmaxf(mx0, fmaxf(sacc[nj][0], sacc[nj][1]));
            mx1 = fmaxf(mx1, fmaxf(sacc[nj][2], sacc[nj][3]));
        }
        mx0 = fmaxf(mx0, __shfl_xor_sync(0xFFFFFFFFu, mx0, 1));
        mx0 = fmaxf(mx0, __shfl_xor_sync(0xFFFFFFFFu, mx0, 2));
        mx1 = fmaxf(mx1, __shfl_xor_sync(0xFFFFFFFFu, mx1, 1));
        mx1 = fmaxf(mx1, __shfl_xor_sync(0xFFFFFFFFu, mx1, 2));

        float mn0 = fmaxf(m0s, mx0), mn1 = fmaxf(m1s, mx1);
        float cr0 = exp2p(m0s - mn0), cr1 = exp2p(m1s - mn1);
        m0s = mn0; m1s = mn1;
        l0s *= cr0; l1s *= cr1;
#pragma unroll
        for (int nj = 0; nj < 8; nj++) {
            ctx[nj][0] *= cr0; ctx[nj][1] *= cr0;
            ctx[nj][2] *= cr1; ctx[nj][3] *= cr1;
        }
        float sum0 = 0.f, sum1 = 0.f;
#pragma unroll
        for (int nj = 0; nj < 8; nj++) {
            float p0 = exp2p(sacc[nj][0] - mn0);
            float p1 = exp2p(sacc[nj][1] - mn0);
            float p2 = exp2p(sacc[nj][2] - mn1);
            float p3 = exp2p(sacc[nj][3] - mn1);
            sum0 += p0 + p1; sum1 += p2 + p3;
            sacc[nj][0] = p0; sacc[nj][1] = p1;
            sacc[nj][2] = p2; sacc[nj][3] = p3;
        }
        sum0 += __shfl_xor_sync(0xFFFFFFFFu, sum0, 1);
        sum0 += __shfl_xor_sync(0xFFFFFFFFu, sum0, 2);
        sum1 += __shfl_xor_sync(0xFFFFFFFFu, sum1, 1);
        sum1 += __shfl_xor_sync(0xFFFFFFFFu, sum1, 2);
        l0s += sum0; l1s += sum1;

        // ---- ctx += P V (P split hi/lo, 3-term) ----
#pragma unroll
        for (int kg = 0; kg < 4; kg++) {
            const float* s0 = sacc[2 * kg];
            const float* s1 = sacc[2 * kg + 1];
            uint32_t ph[4], pl[4];
            ph[0] = prmt_hi(s0[0], s0[1]);
            ph[1] = prmt_hi(s0[2], s0[3]);
            ph[2] = prmt_hi(s1[0], s1[1]);
            ph[3] = prmt_hi(s1[2], s1[3]);
            pl[0] = packlo(s0[0] - hi_trunc(s0[0]), s0[1] - hi_trunc(s0[1]));
            pl[1] = packlo(s0[2] - hi_trunc(s0[2]), s0[3] - hi_trunc(s0[3]));
            pl[2] = packlo(s1[0] - hi_trunc(s1[0]), s1[1] - hi_trunc(s1[1]));
            pl[3] = packlo(s1[2] - hi_trunc(s1[2]), s1[3] - hi_trunc(s1[3]));
            const int rv = kg * 16 + (lane & 15);
#pragma unroll
            for (int dg = 0; dg < 4; dg++) {
                const int cB = dg * 32 + (lane >> 4) * 16;
                uint32_t vh[4], vl[4];
                ldsm4t(vh, sb + 8192 + sw128((uint32_t)(rv * 128 + cB)));
                ldsm4t(vl, sb + 16384 + sw128((uint32_t)(rv * 128 + cB)));
                mma16816(ctx[2 * dg],     ph, vh[0], vh[1]);
                mma16816(ctx[2 * dg + 1], ph, vh[2], vh[3]);
                mma16816(ctx[2 * dg],     ph, vl[0], vl[1]);
                mma16816(ctx[2 * dg + 1], ph, vl[2], vl[3]);
                mma16816(ctx[2 * dg],     pl, vh[0], vh[1]);
                mma16816(ctx[2 * dg + 1], pl, vh[2], vh[3]);
            }
        }
        __syncthreads();
        if (c + 2 < ACH) issue(c + 2, s);
    }

    // ---- write out [b, s, h*64 + d] ----
    const float inv0 = 1.0f / l0s, inv1 = 1.0f / l1s;
    const int r0 = q0 + wid * 16 + (lane >> 2);
    const int dbase = 2 * (lane & 3);
#pragma unroll
    for (int nj = 0; nj < 8; nj++) {
        int d = nj * 8 + dbase;
        float2 v0 = make_float2(ctx[nj][0] * inv0, ctx[nj][1] * inv0);
        float2 v1 = make_float2(ctx[nj][2] * inv1, ctx[nj][3] * inv1);
        *(float2*)&out[(size_t)(b * SS + r0) * HID + h * DD + d] = v0;
        *(float2*)&out[(size_t)(b * SS + r0 + 8) * HID + h * DD + d] = v1;
    }
}

// ===================== launch =====================
extern "C" void kernel_launch(void* const* d_in, const int* in_sizes, int n_in,
                              void* d_out, int out_size) {
    const float* x    = (const float*)d_in[0];
    const int*   mask = (const int*)d_in[1];
    const float* Wq   = (const float*)d_in[2];
    const float* bq   = (const float*)d_in[3];
    const float* Wk   = (const float*)d_in[4];
    const float* bk   = (const float*)d_in[5];
    const float* Wv   = (const float*)d_in[6];
    const float* bv   = (const float*)d_in[7];
    float* out = (float*)d_out;

    static int attr_done = 0;
    if (!attr_done) {
        cudaFuncSetAttribute(qkv_gemm_mma,
                             cudaFuncAttributeMaxDynamicSharedMemorySize, 2 * GSTAGE);
        cudaFuncSetAttribute(attn_mma,
                             cudaFuncAttributeMaxDynamicSharedMemorySize, ASMEM);
        attr_done = 1;
    }

    split_x<<<(NTOK * HID) / 256, 256>>>(x);
    dim3 wgrid(HID / 32, HID / 32, 3);
    split_w<<<wgrid, dim3(32, 32)>>>(Wq, Wk, Wv);

    dim3 ggrid(HID / 64, NTOK / 128, 3);
    qkv_gemm_mma<<<ggrid, 256, 2 * GSTAGE>>>(bq, bk, bv);

    dim3 agrid(SS / 128, HH, BB);
    attn_mma<<<agrid, 256, ASMEM>>>(mask, out);
}

// round 7
// speedup vs baseline: 4.0956x; 1.0610x over previous
#include <cuda_runtime.h>
#include <cuda_bf16.h>
#include <math.h>
#include <stdint.h>

#define BB 2
#define SS 2048
#define HH 16
#define DD 64
#define HID 1024
#define NTOK (BB * SS)
#define LOG2E 1.4426950408889634f
#define QSCALE (0.125f * LOG2E)
#define MASKADD (-10000.0f * LOG2E)

// -------- scratch (allocation-free __device__ globals) --------
__device__ __nv_bfloat16 g_xh[(size_t)NTOK * HID];
__device__ __nv_bfloat16 g_xl[(size_t)NTOK * HID];
__device__ __nv_bfloat16 g_Wth[(size_t)3 * HID * HID];   // W^T [n][k] hi
__device__ __nv_bfloat16 g_Wtl[(size_t)3 * HID * HID];   // W^T [n][k] lo
__device__ __nv_bfloat16 g_Qh[(size_t)NTOK * HID];       // [b][h][s][d]
__device__ __nv_bfloat16 g_Ql[(size_t)NTOK * HID];
__device__ __nv_bfloat16 g_Kh[(size_t)NTOK * HID];
__device__ __nv_bfloat16 g_Vh[(size_t)NTOK * HID];
__device__ __nv_bfloat16 g_Vl[(size_t)NTOK * HID];

// ===================== helpers =====================
__device__ __forceinline__ uint32_t smem_u32(const void* p) {
    uint32_t a;
    asm("{ .reg .u64 t; cvta.to.shared.u64 t, %1; cvt.u32.u64 %0, t; }" : "=r"(a) : "l"(p));
    return a;
}
__device__ __forceinline__ uint32_t sw128(uint32_t o) { return o ^ ((o >> 3) & 0x70); }

__device__ __forceinline__ void ldsm4(uint32_t r[4], uint32_t addr) {
    asm volatile("ldmatrix.sync.aligned.m8n8.x4.shared.b16 {%0,%1,%2,%3}, [%4];"
                 : "=r"(r[0]), "=r"(r[1]), "=r"(r[2]), "=r"(r[3]) : "r"(addr));
}
__device__ __forceinline__ void ldsm4t(uint32_t r[4], uint32_t addr) {
    asm volatile("ldmatrix.sync.aligned.m8n8.x4.trans.shared.b16 {%0,%1,%2,%3}, [%4];"
                 : "=r"(r[0]), "=r"(r[1]), "=r"(r[2]), "=r"(r[3]) : "r"(addr));
}
__device__ __forceinline__ void mma16816(float c[4], const uint32_t a[4],
                                         uint32_t b0, uint32_t b1) {
    asm volatile(
        "mma.sync.aligned.m16n8k16.row.col.f32.bf16.bf16.f32 "
        "{%0,%1,%2,%3}, {%4,%5,%6,%7}, {%8,%9}, {%0,%1,%2,%3};"
        : "+f"(c[0]), "+f"(c[1]), "+f"(c[2]), "+f"(c[3])
        : "r"(a[0]), "r"(a[1]), "r"(a[2]), "r"(a[3]), "r"(b0), "r"(b1));
}
__device__ __forceinline__ uint32_t prmt_hi(float a, float b) {
    uint32_t d;
    asm("prmt.b32 %0, %1, %2, 0x7632;" : "=r"(d)
        : "r"(__float_as_uint(a)), "r"(__float_as_uint(b)));
    return d;
}
__device__ __forceinline__ float hi_trunc(float v) {
    return __uint_as_float(__float_as_uint(v) & 0xFFFF0000u);
}
__device__ __forceinline__ uint32_t packlo(float e0, float e1) {
    uint32_t d;
    asm("cvt.rn.bf16x2.f32 %0, %1, %2;" : "=r"(d) : "f"(e1), "f"(e0));
    return d;
}
// FFMA-only exp2
__device__ __forceinline__ float exp2p(float x) {
    x = fmaxf(x, -100.0f);
    float t = x + 12582912.0f;
    int   k = __float_as_int(t) - 0x4B400000;
    float f = x - (t - 12582912.0f);
    float r = 1.3333558146428443e-3f;
    r = fmaf(r, f, 9.618129107628477e-3f);
    r = fmaf(r, f, 5.550410866482158e-2f);
    r = fmaf(r, f, 2.402265069591007e-1f);
    r = fmaf(r, f, 6.931471805599453e-1f);
    r = fmaf(r, f, 1.0f);
    return r * __int_as_float(0x3F800000 + (k << 23));
}
__device__ __forceinline__ void cpa16(uint32_t s, const void* g) {
    asm volatile("cp.async.cg.shared.global [%0], [%1], 16;" :: "r"(s), "l"(g));
}
__device__ __forceinline__ void cpa4(uint32_t s, const void* g) {
    asm volatile("cp.async.ca.shared.global [%0], [%1], 4;" :: "r"(s), "l"(g));
}
#define CPA_COMMIT() asm volatile("cp.async.commit_group;")
#define CPA_WAIT2()  asm volatile("cp.async.wait_group 2;")
#define CPA_WAIT1()  asm volatile("cp.async.wait_group 1;")
#define CPA_WAIT0()  asm volatile("cp.async.wait_group 0;")

// ===================== prep kernels (RN hi, residual lo) =====================
__global__ void split_x(const float* __restrict__ x) {
    int i = blockIdx.x * 256 + threadIdx.x;
    float v = x[i];
    __nv_bfloat16 h = __float2bfloat16(v);
    g_xh[i] = h;
    g_xl[i] = __float2bfloat16(v - __bfloat162float(h));
}

__global__ void split_w(const float* __restrict__ Wq, const float* __restrict__ Wk,
                        const float* __restrict__ Wv) {
    __shared__ float t[32][33];
    int z = blockIdx.z;
    const float* W = (z == 0) ? Wq : (z == 1) ? Wk : Wv;
    int tx = threadIdx.x, ty = threadIdx.y;
    t[ty][tx] = W[(size_t)(blockIdx.y * 32 + ty) * HID + blockIdx.x * 32 + tx];
    __syncthreads();
    int n = blockIdx.x * 32 + ty;
    int k = blockIdx.y * 32 + tx;
    float v = t[tx][ty];
    __nv_bfloat16 h = __float2bfloat16(v);
    size_t o = (size_t)z * HID * HID + (size_t)n * HID + k;
    g_Wth[o] = h;
    g_Wtl[o] = __float2bfloat16(v - __bfloat162float(h));
}

// ===================== QKV GEMM (mma.sync, 2-stage cp.async) =====================
// BM=128, BN=64, BK=64. stage: Ah@0(16K) Al@16K Bh@32K Bl@40K = 48K; 2 stages.
#define GSTAGE 49152
#define NCHUNK 16

__global__ __launch_bounds__(256, 2)
void qkv_gemm_mma(const float* __restrict__ bq, const float* __restrict__ bk,
                  const float* __restrict__ bv) {
    extern __shared__ __align__(1024) char sm[];
    const int tid = threadIdx.x, lane = tid & 31, wid = tid >> 5;
    const int wm = wid & 3, wn = wid >> 2;
    const int z = blockIdx.z;
    const int m0 = blockIdx.y * 128;
    const int n0 = blockIdx.x * 64;

    const __nv_bfloat16* Wh = g_Wth + (size_t)z * HID * HID;
    const __nv_bfloat16* Wl = g_Wtl + (size_t)z * HID * HID;
    const float* bias = (z == 0) ? bq : (z == 1) ? bk : bv;
    const uint32_t smb = smem_u32(sm);

    auto issue = [&](int c, int s) {
        const uint32_t sb = smb + s * GSTAGE;
        const int k0 = c * 64;
#pragma unroll
        for (int j = 0; j < 4; j++) {
            int idx = tid + 256 * j;
            int row = idx >> 3, ch = idx & 7;
            uint32_t so = sw128((uint32_t)(row * 128 + ch * 16));
            size_t ga = (size_t)(m0 + row) * HID + k0 + ch * 8;
            cpa16(sb + so,         g_xh + ga);
            cpa16(sb + 16384 + so, g_xl + ga);
        }
#pragma unroll
        for (int j = 0; j < 2; j++) {
            int idx = tid + 256 * j;
            int row = idx >> 3, ch = idx & 7;
            uint32_t so = sw128((uint32_t)(row * 128 + ch * 16));
            size_t gb = (size_t)(n0 + row) * HID + k0 + ch * 8;
            cpa16(sb + 32768 + so, Wh + gb);
            cpa16(sb + 40960 + so, Wl + gb);
        }
        CPA_COMMIT();
    };

    float acc[2][4][4];
#pragma unroll
    for (int i = 0; i < 2; i++)
#pragma unroll
        for (int j = 0; j < 4; j++)
#pragma unroll
            for (int v = 0; v < 4; v++) acc[i][j][v] = 0.f;

    issue(0, 0);
    issue(1, 1);

    const int rA = wm * 32 + (lane & 15);
    const int rB = wn * 32 + (lane & 15);

    for (int c = 0; c < NCHUNK; c++) {
        const int s = c & 1;
        const uint32_t sb = smb + s * GSTAGE;
        if (c + 2 < NCHUNK) CPA_WAIT1(); else CPA_WAIT0();
        __syncthreads();

#pragma unroll
        for (int kk = 0; kk < 4; kk++) {
            const int cB = kk * 32 + (lane >> 4) * 16;
            const uint32_t aA = sb + sw128((uint32_t)(rA * 128 + cB));
            const uint32_t aB = sb + 32768 + sw128((uint32_t)(rB * 128 + cB));
            uint32_t ah[2][4], al[2][4], bh[2][4], bl[2][4];
            ldsm4(ah[0], aA);            ldsm4(ah[1], aA + 2048);
            ldsm4(al[0], aA + 16384);    ldsm4(al[1], aA + 18432);
            ldsm4(bh[0], aB);            ldsm4(bh[1], aB + 2048);
            ldsm4(bl[0], aB + 8192);     ldsm4(bl[1], aB + 10240);
#pragma unroll
            for (int g = 0; g < 2; g++) {
#pragma unroll
                for (int mi = 0; mi < 2; mi++) {
                    mma16816(acc[mi][2 * g],     ah[mi], bh[g][0], bh[g][2]);
                    mma16816(acc[mi][2 * g + 1], ah[mi], bh[g][1], bh[g][3]);
                    mma16816(acc[mi][2 * g],     ah[mi], bl[g][0], bl[g][2]);
                    mma16816(acc[mi][2 * g + 1], ah[mi], bl[g][1], bl[g][3]);
                    mma16816(acc[mi][2 * g],     al[mi], bh[g][0], bh[g][2]);
                    mma16816(acc[mi][2 * g + 1], al[mi], bh[g][1], bh[g][3]);
                }
            }
        }
        __syncthreads();
        if (c + 2 < NCHUNK) issue(c + 2, s);
    }

    // epilogue: bias (+Q scale), RN hi + residual lo, store [b,h,s,d]
    __nv_bfloat16* outh = (z == 0) ? g_Qh : (z == 1) ? g_Kh : g_Vh;
    __nv_bfloat16* outl = (z == 0) ? g_Ql : g_Vl;   // z==1 lo never consumed
    const float sc = (z == 0) ? QSCALE : 1.0f;
#pragma unroll
    for (int mi = 0; mi < 2; mi++) {
        int r0 = m0 + wm * 32 + mi * 16 + (lane >> 2);
#pragma unroll
        for (int nj = 0; nj < 4; nj++) {
            int col = n0 + wn * 32 + nj * 8 + 2 * (lane & 3);
            float b0v = __ldg(&bias[col]), b1v = __ldg(&bias[col + 1]);
#pragma unroll
            for (int half = 0; half < 2; half++) {
                int r = r0 + half * 8;
                float v0 = (acc[mi][nj][half * 2 + 0] + b0v) * sc;
                float v1 = (acc[mi][nj][half * 2 + 1] + b1v) * sc;
                size_t off = (((size_t)((r >> 11) * HH + (col >> 6)) * SS +
                               (r & (SS - 1))) * DD) + (col & (DD - 1));
                uint32_t hp = packlo(v0, v1);
                *(uint32_t*)(outh + off) = hp;
                if (z != 1) {
                    float hf0 = __uint_as_float(hp << 16);
                    float hf1 = __uint_as_float(hp & 0xFFFF0000u);
                    *(uint32_t*)(outl + off) = packlo(v0 - hf0, v1 - hf1);
                }
            }
        }
    }
}

// ===================== flash attention (3-stage cp.async, no online max) =====================
// CTA: 128 q rows, 8 warps. 64 keys/chunk, 32 chunks.
// stage s@s*24576: Kh@0(8K) Vh@8192 Vl@16384. mask ints @73728+s*256.
#define ASTAGE 24576
#define AADDER (3 * ASTAGE)          // 73728
#define ASMEM  (AADDER + 3 * 256)    // 74496
#define ACH 32

__global__ __launch_bounds__(256, 2)
void attn_mma(const int* __restrict__ mask, float* __restrict__ out) {
    extern __shared__ __align__(1024) char sm[];
    const int tid = threadIdx.x, lane = tid & 31, wid = tid >> 5;
    const int q0 = blockIdx.x * 128;
    const int h = blockIdx.y, b = blockIdx.z;
    const size_t hb = (size_t)(b * HH + h) * SS * DD;
    const uint32_t smb = smem_u32(sm);

    // ---- prologue: stage Q hi/lo, read A-frags ----
#pragma unroll
    for (int j = 0; j < 4; j++) {
        int idx = tid + 256 * j;
        int row = idx >> 3, ch = idx & 7;
        uint32_t so = sw128((uint32_t)(row * 128 + ch * 16));
        size_t g = hb + (size_t)(q0 + row) * DD + ch * 8;
        *(uint4*)(sm + so)         = *(const uint4*)(g_Qh + g);
        *(uint4*)(sm + 16384 + so) = *(const uint4*)(g_Ql + g);
    }
    __syncthreads();
    uint32_t qh[4][4], ql[4][4];
    {
        int r = wid * 16 + (lane & 15);
#pragma unroll
        for (int kk = 0; kk < 4; kk++) {
            int cB = kk * 32 + (lane >> 4) * 16;
            uint32_t qa = smb + sw128((uint32_t)(r * 128 + cB));
            ldsm4(qh[kk], qa);
            ldsm4(ql[kk], qa + 16384);
        }
    }
    __syncthreads();

    auto issue = [&](int c, int s) {
        const uint32_t sb = smb + s * ASTAGE;
        const int c0 = c * 64;
#pragma unroll
        for (int j = 0; j < 2; j++) {
            int idx = tid + 256 * j;
            int row = idx >> 3, ch = idx & 7;
            uint32_t so = sw128((uint32_t)(row * 128 + ch * 16));
            size_t g = hb + (size_t)(c0 + row) * DD + ch * 8;
            cpa16(sb + so,         g_Kh + g);
            cpa16(sb + 8192 + so,  g_Vh + g);
            cpa16(sb + 16384 + so, g_Vl + g);
        }
        if (tid < 64) cpa4(smb + AADDER + s * 256 + tid * 4, mask + b * SS + c0 + tid);
        CPA_COMMIT();
    };

    float ctx[8][4];
#pragma unroll
    for (int i = 0; i < 8; i++)
#pragma unroll
        for (int j = 0; j < 4; j++) ctx[i][j] = 0.f;
    float l0s = 0.f, l1s = 0.f;

    issue(0, 0); issue(1, 1); issue(2, 2);

    const int rk = lane & 15;
    const int kcol = 2 * (lane & 3);

    for (int c = 0; c < ACH; c++) {
        const int s = c % 3;
        const uint32_t sb = smb + s * ASTAGE;
        if (c <= ACH - 3) CPA_WAIT2();
        else if (c == ACH - 2) CPA_WAIT1();
        else CPA_WAIT0();
        __syncthreads();

        // ---- S = Q K^T (2-term: qh*kh + ql*kh) ----
        float sacc[8][4];
#pragma unroll
        for (int i = 0; i < 8; i++)
#pragma unroll
            for (int j = 0; j < 4; j++) sacc[i][j] = 0.f;

#pragma unroll
        for (int kk = 0; kk < 4; kk++) {
            const int cB = kk * 32 + (lane >> 4) * 16;
            const uint32_t ka = sb + sw128((uint32_t)(rk * 128 + cB));
#pragma unroll
            for (int g = 0; g < 4; g++) {
                uint32_t kh[4];
                ldsm4(kh, ka + g * 2048);
                mma16816(sacc[2 * g],     qh[kk], kh[0], kh[2]);
                mma16816(sacc[2 * g + 1], qh[kk], kh[1], kh[3]);
                mma16816(sacc[2 * g],     ql[kk], kh[0], kh[2]);
                mma16816(sacc[2 * g + 1], ql[kk], kh[1], kh[3]);
            }
        }

        // ---- softmax numerator, fixed base (scores provably small) ----
        const int* madd = (const int*)(sm + AADDER + s * 256);
#pragma unroll
        for (int nj = 0; nj < 8; nj++) {
            float a0 = madd[nj * 8 + kcol]     ? 0.f : MASKADD;
            float a1 = madd[nj * 8 + kcol + 1] ? 0.f : MASKADD;
            float p0 = exp2p(sacc[nj][0] + a0);
            float p1 = exp2p(sacc[nj][1] + a1);
            float p2 = exp2p(sacc[nj][2] + a0);
            float p3 = exp2p(sacc[nj][3] + a1);
            l0s += p0 + p1; l1s += p2 + p3;
            sacc[nj][0] = p0; sacc[nj][1] = p1;
            sacc[nj][2] = p2; sacc[nj][3] = p3;
        }

        // ---- pack P (trunc hi + residual lo) ----
        uint32_t ph[4][4], pl[4][4];
#pragma unroll
        for (int kg = 0; kg < 4; kg++) {
            const float* s0 = sacc[2 * kg];
            const float* s1 = sacc[2 * kg + 1];
            ph[kg][0] = prmt_hi(s0[0], s0[1]);
            ph[kg][1] = prmt_hi(s0[2], s0[3]);
            ph[kg][2] = prmt_hi(s1[0], s1[1]);
            ph[kg][3] = prmt_hi(s1[2], s1[3]);
            pl[kg][0] = packlo(s0[0] - hi_trunc(s0[0]), s0[1] - hi_trunc(s0[1]));
            pl[kg][1] = packlo(s0[2] - hi_trunc(s0[2]), s0[3] - hi_trunc(s0[3]));
            pl[kg][2] = packlo(s1[0] - hi_trunc(s1[0]), s1[1] - hi_trunc(s1[1]));
            pl[kg][3] = packlo(s1[2] - hi_trunc(s1[2]), s1[3] - hi_trunc(s1[3]));
        }

        // ---- ctx += P V (3-term) ----
#pragma unroll
        for (int dg = 0; dg < 4; dg++) {
            const int cB = dg * 32 + (lane >> 4) * 16;
            const uint32_t va = sb + 8192 + sw128((uint32_t)((lane & 15) * 128 + cB));
#pragma unroll
            for (int kg = 0; kg < 4; kg++) {
                uint32_t vh[4], vl[4];
                ldsm4t(vh, va + kg * 2048);
                ldsm4t(vl, va + 8192 + kg * 2048);
                mma16816(ctx[2 * dg],     ph[kg], vh[0], vh[1]);
                mma16816(ctx[2 * dg + 1], ph[kg], vh[2], vh[3]);
                mma16816(ctx[2 * dg],     ph[kg], vl[0], vl[1]);
                mma16816(ctx[2 * dg + 1], ph[kg], vl[2], vl[3]);
                mma16816(ctx[2 * dg],     pl[kg], vh[0], vh[1]);
                mma16816(ctx[2 * dg + 1], pl[kg], vh[2], vh[3]);
            }
        }
        __syncthreads();
        if (c + 3 < ACH) issue(c + 3, (c + 3) % 3);
    }

    // ---- l reduction across the quad, then write out ----
    l0s += __shfl_xor_sync(0xFFFFFFFFu, l0s, 1);
    l0s += __shfl_xor_sync(0xFFFFFFFFu, l0s, 2);
    l1s += __shfl_xor_sync(0xFFFFFFFFu, l1s, 1);
    l1s += __shfl_xor_sync(0xFFFFFFFFu, l1s, 2);
    const float inv0 = 1.0f / l0s, inv1 = 1.0f / l1s;
    const int r0 = q0 + wid * 16 + (lane >> 2);
    const int dbase = 2 * (lane & 3);
#pragma unroll
    for (int nj = 0; nj < 8; nj++) {
        int d = nj * 8 + dbase;
        float2 v0 = make_float2(ctx[nj][0] * inv0, ctx[nj][1] * inv0);
        float2 v1 = make_float2(ctx[nj][2] * inv1, ctx[nj][3] * inv1);
        *(float2*)&out[(size_t)(b * SS + r0) * HID + h * DD + d] = v0;
        *(float2*)&out[(size_t)(b * SS + r0 + 8) * HID + h * DD + d] = v1;
    }
}

// ===================== launch =====================
extern "C" void kernel_launch(void* const* d_in, const int* in_sizes, int n_in,
                              void* d_out, int out_size) {
    const float* x    = (const float*)d_in[0];
    const int*   mask = (const int*)d_in[1];
    const float* Wq   = (const float*)d_in[2];
    const float* bq   = (const float*)d_in[3];
    const float* Wk   = (const float*)d_in[4];
    const float* bk   = (const float*)d_in[5];
    const float* Wv   = (const float*)d_in[6];
    const float* bv   = (const float*)d_in[7];
    float* out = (float*)d_out;

    static int attr_done = 0;
    if (!attr_done) {
        cudaFuncSetAttribute(qkv_gemm_mma,
                             cudaFuncAttributeMaxDynamicSharedMemorySize, 2 * GSTAGE);
        cudaFuncSetAttribute(attn_mma,
                             cudaFuncAttributeMaxDynamicSharedMemorySize, ASMEM);
        attr_done = 1;
    }

    split_x<<<(NTOK * HID) / 256, 256>>>(x);
    dim3 wgrid(HID / 32, HID / 32, 3);
    split_w<<<wgrid, dim3(32, 32)>>>(Wq, Wk, Wv);

    dim3 ggrid(HID / 64, NTOK / 128, 3);
    qkv_gemm_mma<<<ggrid, 256, 2 * GSTAGE>>>(bq, bk, bv);

    dim3 agrid(SS / 128, HH, BB);
    attn_mma<<<agrid, 256, ASMEM>>>(mask, out);
}